// round 1
// baseline (speedup 1.0000x reference)
#include <cuda_runtime.h>
#include <cuda_bf16.h>
#include <cstdint>

// HilbertSchmidtVQ forward:
//   out = rho_flat + (quantized - stop_gradient(quantized))
// stop_gradient is a value-identity, so (q - q) == 0 bitwise and
// out == rho_flat exactly. The distance/argmin/gather affect gradients only.
// The forward kernel is therefore a pure device-to-device copy of rho_flat,
// and the roofline-optimal implementation is a streaming bandwidth copy.
//
// N=65536, DIM=256 -> 16,777,216 floats = 4,194,304 float4.

__global__ __launch_bounds__(256) void vq_forward_copy_kernel(
    const float4* __restrict__ src, float4* __restrict__ dst, int n_vec)
{
    int i = blockIdx.x * blockDim.x + threadIdx.x;
    int stride = gridDim.x * blockDim.x;
    for (; i < n_vec; i += stride) {
        dst[i] = src[i];
    }
}

extern "C" void kernel_launch(void* const* d_in, const int* in_sizes, int n_in,
                              void* d_out, int out_size) {
    // in[0] = rho_flat (N*DIM floats), in[1] = codebook (K*DIM floats, unused)
    const float4* src = (const float4*)d_in[0];
    float4* dst = (float4*)d_out;

    const int n_vec = out_size / 4;  // out_size = N*DIM floats, /4 for float4

    // One float4 per thread, enough blocks to cover; grid-stride handles remainder.
    const int threads = 256;
    const int blocks = (n_vec + threads - 1) / threads;  // 16384 blocks
    vq_forward_copy_kernel<<<blocks, threads>>>(src, dst, n_vec);
}

// round 2
// speedup vs baseline: 1.3623x; 1.3623x over previous
#include <cuda_runtime.h>
#include <cuda_bf16.h>
#include <cstdint>

// HilbertSchmidtVQ forward: out == rho_flat bitwise (q - stop_grad(q) == 0).
// Roofline-optimal implementation is a streaming copy.
//
// R2 changes vs R1:
//  - 8x unroll, front-batched independent 128-bit loads (MLP=8/thread)
//  - stores use .cs (evict-first) so the read stream can stay L2-resident
//    across graph replays (input 64 MiB < L2 ~126 MB, never written)
//  - exact grid: 2048 CTAs x 256 thr x 8 float4 = 4,194,304 float4 = 64 MiB

#define UNROLL 8

__global__ __launch_bounds__(256) void vq_forward_copy_kernel(
    const float4* __restrict__ src, float4* __restrict__ dst, int n_vec)
{
    // Coalesced tiling: each CTA owns a contiguous span of blockDim*UNROLL
    // float4s; within it, thread t handles t + k*blockDim (k=0..UNROLL-1).
    int base = blockIdx.x * (blockDim.x * UNROLL) + threadIdx.x;

    float4 v[UNROLL];
    bool ok[UNROLL];

    // Front-batch all loads (independent addresses -> MLP=UNROLL).
#pragma unroll
    for (int k = 0; k < UNROLL; ++k) {
        int i = base + k * blockDim.x;
        ok[k] = (i < n_vec);
        if (ok[k]) v[k] = src[i];
    }

    // Evict-first stores: keep L2 for the (reused-across-replays) read stream.
#pragma unroll
    for (int k = 0; k < UNROLL; ++k) {
        int i = base + k * blockDim.x;
        if (ok[k]) {
            asm volatile("st.global.cs.v4.f32 [%0], {%1, %2, %3, %4};"
                         :: "l"(dst + i),
                            "f"(v[k].x), "f"(v[k].y), "f"(v[k].z), "f"(v[k].w)
                         : "memory");
        }
    }
}

extern "C" void kernel_launch(void* const* d_in, const int* in_sizes, int n_in,
                              void* d_out, int out_size) {
    const float4* src = (const float4*)d_in[0];
    float4* dst = (float4*)d_out;

    const int n_vec = out_size / 4;          // 4,194,304 float4
    const int threads = 256;
    const int per_cta = threads * UNROLL;    // 2048 float4 per CTA
    const int blocks = (n_vec + per_cta - 1) / per_cta;  // 2048 CTAs
    vq_forward_copy_kernel<<<blocks, threads>>>(src, dst, n_vec);
}